// round 17
// baseline (speedup 1.0000x reference)
#include <cuda_runtime.h>

#define N_SAMPLES 32768
#define N_ITERS   16
#define KLEN      256
#define N_FRAMES  512
#define N_ATOMS   256
#define THREADS   1024
#define STEP      (N_SAMPLES / N_FRAMES)   // 64
#define N_VEC4    (N_SAMPLES / 4)          // 8192 float4s
#define W_VEC4    (KLEN / 4)               // 64 float4s per window
#define ZERO_BLOCKS 8
#define GRID      (1 + ZERO_BLOCKS)

// Monotone map: float bits -> u32 preserving < order (handles negatives).
__device__ __forceinline__ unsigned fkey(float v)
{
    unsigned u = __float_as_uint(v);
    return (u & 0x80000000u) ? ~u : (u | 0x80000000u);
}

// Vectorized warp argmax over NV float4s per lane (row length NV*128 floats).
// Within-lane: TOURNAMENT reduction (depth log2(4*NV) instead of a serial
// 4*NV-node compare-select chain). Lexicographic (value, then smaller index)
// merge == first-occurrence argmax (jnp.argmax semantics). All array indices
// are compile-time after full unroll -> stays in registers (no LMEM demotion).
// Across lanes: redux_max on monotone key, redux_min over tied indices.
template <int NV>
__device__ __forceinline__ int warp_argmax_vec(const float4* __restrict__ row4, int lane)
{
    float4 rv[NV];
    #pragma unroll
    for (int c = 0; c < NV; c++) rv[c] = row4[lane + 32 * c];   // front-batched LDGs

    float v[NV * 4];
    int   ix[NV * 4];
    #pragma unroll
    for (int c = 0; c < NV; c++) {
        const int base = (lane + 32 * c) * 4;
        v[c*4+0] = rv[c].x; ix[c*4+0] = base + 0;
        v[c*4+1] = rv[c].y; ix[c*4+1] = base + 1;
        v[c*4+2] = rv[c].z; ix[c*4+2] = base + 2;
        v[c*4+3] = rv[c].w; ix[c*4+3] = base + 3;
    }
    // pairwise tournament: log2(4*NV) levels, nodes within a level independent
    #pragma unroll
    for (int s = NV * 2; s >= 1; s >>= 1) {
        #pragma unroll
        for (int k = 0; k < s; k++) {
            const bool t = (v[k+s] > v[k]) || (v[k+s] == v[k] && ix[k+s] < ix[k]);
            v[k]  = t ? v[k+s]  : v[k];
            ix[k] = t ? ix[k+s] : ix[k];
        }
    }
    const unsigned key  = fkey(v[0]);
    const unsigned wmax = __reduce_max_sync(0xffffffffu, key);
    const unsigned cand = (key == wmax) ? (unsigned)ix[0] : 0xffffffffu;
    return (int)__reduce_min_sync(0xffffffffu, cand);
}

__global__ __launch_bounds__(THREADS, 1)
void Model_67817533604348_kernel(const float* __restrict__ atom_sel,   // [16,256]
                                 const float* __restrict__ amps,       // [16,1]
                                 const float* __restrict__ sched,      // [16,512]
                                 const float* __restrict__ d,          // [256,256]
                                 float* __restrict__ out)              // [32768]
{
    __shared__ float s_atoms[N_ITERS][KLEN];   // 16 KB: amp-scaled selected rows
    __shared__ int   s_pos[N_ITERS];           // block0: sample pos; zero: float4 pos
    __shared__ float s_red[32];

    const int tid  = threadIdx.x;
    const int wid  = tid >> 5;
    const int lane = tid & 31;

    if (blockIdx.x != 0) {
        // ================= ZERO-WRITER BLOCKS (addresses disjoint from block 0) ==
        if (wid < N_ITERS) {
            int bi = warp_argmax_vec<4>((const float4*)(sched + wid * N_FRAMES), lane);
            if (lane == 0) s_pos[wid] = (bi * STEP) >> 2;   // window start, float4s
        }
        __syncthreads();

        const int v = (int)(blockIdx.x - 1) * THREADS + tid;   // float4 idx [0,8192)
        bool covered = false;
        #pragma unroll
        for (int i = 0; i < N_ITERS; i++)
            covered |= ((unsigned)(v - s_pos[i]) < (unsigned)W_VEC4);
        if (!covered)
            reinterpret_cast<float4*>(out)[v] = make_float4(0.f, 0.f, 0.f, 0.f);
        return;
    }

    // ================= COMPUTE BLOCK: windows only ============================
    // Warp w < 16: full pipeline for iter w — atom argmax -> fetch d row ->
    //              amp-scale -> stage to smem. (soft_dirac fwd = exact one-hot
    //              at argmax; softmax monotone -> raw-logit argmax suffices.)
    // Warp w >= 16: sched argmax for iter w-16 -> s_pos.
    if (wid < N_ITERS) {
        const int aidx = warp_argmax_vec<2>((const float4*)(atom_sel + wid * N_ATOMS),
                                            lane);
        const float amp = amps[wid];                       // broadcast LDG
        const float4* drow = (const float4*)(d + aidx * KLEN);
        const float4 d0 = drow[lane];                      // taps [4*lane, 4*lane+4)
        const float4 d1 = drow[lane + 32];                 // taps +128
        *reinterpret_cast<float4*>(&s_atoms[wid][lane * 4]) =
            make_float4(amp * d0.x, amp * d0.y, amp * d0.z, amp * d0.w);
        *reinterpret_cast<float4*>(&s_atoms[wid][lane * 4 + 128]) =
            make_float4(amp * d1.x, amp * d1.y, amp * d1.z, amp * d1.w);
    } else {
        const int i = wid - N_ITERS;
        int bi = warp_argmax_vec<4>((const float4*)(sched + i * N_FRAMES), lane);
        if (lane == 0) s_pos[i] = bi * STEP;   // sample position (multiple of 64)
    }
    __syncthreads();

    // Gather: exactly one float4 of one window per thread. s0 - p_j is a
    // multiple of 4 (positions are multiples of 64) -> aligned LDS.128,
    // conflict-free. s_pos[j] reads use compile-time j (cheap broadcast LDS).
    // Overlapping windows give bitwise-identical duplicates — benign.
    const int it = tid >> 6;            // iter (64 threads per iter)
    const int k0 = (tid & 63) << 2;     // first tap, multiple of 4
    const int s0 = s_pos[it] + k0;
    float4 acc = make_float4(0.f, 0.f, 0.f, 0.f);
    #pragma unroll
    for (int j = 0; j < N_ITERS; j++) {
        const int off = s0 - s_pos[j];
        if ((unsigned)off < (unsigned)KLEN) {
            const float4 a = *reinterpret_cast<const float4*>(&s_atoms[j][off]);
            acc.x += a.x; acc.y += a.y; acc.z += a.z; acc.w += a.w;
        }
    }
    const bool ok = s0 < N_SAMPLES;   // truncated tail dropped (float4-aligned cut)

    // Block max-abs reduce. Values are non-negative -> float bits compare as
    // u32, so redux.sync.max works directly. Stage 2 is done redundantly by
    // EVERY warp (each lane reads s_red[lane]) — no s_scale bounce, no 3rd BAR.
    float mx = ok ? fmaxf(fmaxf(fabsf(acc.x), fabsf(acc.y)),
                          fmaxf(fabsf(acc.z), fabsf(acc.w))) : 0.0f;
    mx = __uint_as_float(__reduce_max_sync(0xffffffffu, __float_as_uint(mx)));
    if (lane == 0) s_red[wid] = mx;
    __syncthreads();
    const float m = __uint_as_float(
        __reduce_max_sync(0xffffffffu, __float_as_uint(s_red[lane])));
    const float scale = 1.0f / (m + 1e-8f);

    // Store ONLY window float4s (disjoint from zero-writers; duplicates on
    // overlapping windows carry identical bits — benign).
    if (ok) {
        acc.x *= scale; acc.y *= scale; acc.z *= scale; acc.w *= scale;
        *reinterpret_cast<float4*>(&out[s0]) = acc;
    }
}

extern "C" void kernel_launch(void* const* d_in, const int* in_sizes, int n_in,
                              void* d_out, int out_size) {
    // metadata order: x (unused), atom_selection, amps, sched_params, d
    const float* atom_sel = (const float*)d_in[1];
    const float* amps     = (const float*)d_in[2];
    const float* sched    = (const float*)d_in[3];
    const float* d        = (const float*)d_in[4];
    float* out            = (float*)d_out;

    Model_67817533604348_kernel<<<GRID, THREADS>>>(atom_sel, amps, sched, d, out);
}